// round 9
// baseline (speedup 1.0000x reference)
#include <cuda_runtime.h>

#define NLEV 4
#define KCB  256
#define DIM  128
#define ROWS 32                  // rows per block (1 warp-row-group of 8 per warp)
#define TPB  128
#define KQ    16                 // k-slice per staged chunk
#define CHUNKF (KQ * KCB)        // 4096 floats = 16 KB per chunk
#define NCHUNK (NLEV * (DIM / KQ))  // 32 chunks total

// Scratch (allocation-free rule: __device__ globals).
__device__ float g_cbT[NLEV * DIM * KCB];   // [l][k][e], k-slice contiguous
__device__ float g_cnorm[NLEV * KCB];

// ---------------------------------------------------------------------------
// Prep: transposed codebook + per-entry squared norms.
// ---------------------------------------------------------------------------
__global__ void rq_prep_kernel(const float* __restrict__ cb) {
    int i = blockIdx.x * blockDim.x + threadIdx.x;
    const int total = NLEV * KCB * DIM;
    if (i < total) {
        int l   = i / (KCB * DIM);
        int rem = i - l * (KCB * DIM);
        int e   = rem >> 7;
        int k   = rem & 127;
        g_cbT[l * (DIM * KCB) + k * KCB + e] = cb[i];
    }
    if (i < NLEV * KCB) {
        const float* p = cb + (size_t)i * DIM;
        float s = 0.0f;
        #pragma unroll 1
        for (int k = 0; k < DIM; k++) s = fmaf(p[k], p[k], s);
        g_cnorm[i] = s;
    }
}

__device__ __forceinline__ void cp16(float* s, const float* g) {
    unsigned sa = (unsigned)__cvta_generic_to_shared(s);
    asm volatile("cp.async.cg.shared.global [%0], [%1], 16;" :: "r"(sa), "l"(g));
}

// FFMA2 block: 8 rows x 4 entry-pairs against one k of codebook.
// k consumed strictly ascending -> accumulation order identical to prior rounds.
#define GEMM_STEP(RV, CA, CB)                                                          \
    {                                                                                  \
        _Pragma("unroll")                                                              \
        for (int r = 0; r < 8; r++) {                                                  \
            unsigned long long rr;                                                     \
            asm("mov.b64 %0, {%1, %1};" : "=l"(rr) : "r"(__float_as_uint(RV[r])));     \
            asm("fma.rn.f32x2 %0, %1, %2, %0;" : "+l"(acc[r][0]) : "l"(rr), "l"(CA.x));\
            asm("fma.rn.f32x2 %0, %1, %2, %0;" : "+l"(acc[r][1]) : "l"(rr), "l"(CA.y));\
            asm("fma.rn.f32x2 %0, %1, %2, %0;" : "+l"(acc[r][2]) : "l"(rr), "l"(CB.x));\
            asm("fma.rn.f32x2 %0, %1, %2, %0;" : "+l"(acc[r][3]) : "l"(rr), "l"(CB.y));\
        }                                                                              \
    }

#define LOAD_C(CA, CB, KI)                                                             \
    {                                                                                  \
        const float* _p = bufp + (KI) * KCB;                                           \
        CA = *(const ulonglong2*)_p;                                                   \
        CB = *(const ulonglong2*)(_p + 128);                                           \
    }

#define LOAD_RF(RF, KI)                                                                \
    {                                                                                  \
        _Pragma("unroll")                                                              \
        for (int r = 0; r < 8; r++)                                                    \
            RF[r] = *(const float2*)(resp + r * DIM + (KI));                           \
    }

// ---------------------------------------------------------------------------
// Main fused RQ kernel — 4 independent blocks/SM (128 thr, 52 KB smem, <=128 regs).
// Per-thread work identical to R7 (8 rows x 8 entries, 4-phase pipelined GEMM);
// smaller blocks decorrelate barrier/epilogue stalls across 4 domains per SM.
// ---------------------------------------------------------------------------
extern __shared__ float smem_dyn[];

__global__ void __launch_bounds__(TPB, 4)
rq_main_kernel(const float* __restrict__ x,
               const float* __restrict__ cb,        // [l][e][k] original
               float* __restrict__ out_recon,
               float* __restrict__ out_codes,
               int write_codes) {
    float* shBuf = smem_dyn;                    // 2 * 4096 floats (double buffer)
    float* shRes = smem_dyn + 2 * CHUNKF;       // ROWS*DIM = 4096 floats
    float* shCn  = shRes + ROWS * DIM;          // NLEV*KCB = 1024 floats

    const int tid   = threadIdx.x;
    const int lane  = tid & 31;
    const int warp  = tid >> 5;
    const long long row0 = (long long)blockIdx.x * ROWS;
    const int rbase = warp * 8;      // 4 warps * 8 rows = 32
    const int e0    = lane * 4;      // quad A base; quad B base = 128 + e0

    // all levels' cnorms -> smem (1024 floats, two float4 per thread)
    ((float4*)shCn)[tid]       = ((const float4*)g_cnorm)[tid];
    ((float4*)shCn)[tid + TPB] = ((const float4*)g_cnorm)[tid + TPB];

    const float4* x4   = (const float4*)(x + row0 * DIM);
    float4*       res4 = (float4*)shRes;
    #pragma unroll
    for (int i = 0; i < (ROWS * DIM / 4) / TPB; i++)   // 8
        res4[tid + i * TPB] = x4[tid + i * TPB];

    // prologue: prefetch chunks 0,1
    #pragma unroll
    for (int c = 0; c < 2; c++) {
        const float* g = g_cbT + (size_t)c * CHUNKF;
        float*       s = shBuf + (c & 1) * CHUNKF;
        #pragma unroll
        for (int i = 0; i < CHUNKF / 4 / TPB; i++)     // 8
            cp16(s + (size_t)(tid + i * TPB) * 4, g + (size_t)(tid + i * TPB) * 4);
        asm volatile("cp.async.commit_group;");
    }

    for (int l = 0; l < NLEV; l++) {
        unsigned long long acc[8][4];
        #pragma unroll
        for (int r = 0; r < 8; r++) {
            acc[r][0] = 0ull; acc[r][1] = 0ull; acc[r][2] = 0ull; acc[r][3] = 0ull;
        }

        #pragma unroll 1
        for (int q = 0; q < DIM / KQ; q++) {           // 8 slices per level
            const int c = (DIM / KQ) * l + q;
            // one group committed per slice -> "<=1 pending" => chunk c landed
            asm volatile("cp.async.wait_group 1;" ::: "memory");
            __syncthreads();

            const float* bufp = shBuf + (c & 1) * CHUNKF + e0;
            const float* resp = shRes + rbase * DIM + q * KQ;

            // 4-phase pipeline: every LDS lands one FFMA2 block before use.
            float2 rfA[8], rfB[8];
            ulonglong2 c0A, c0B, c1A, c1B;
            float rvx[8];
            LOAD_RF(rfA, 0);
            LOAD_C(c0A, c0B, 0);

            #pragma unroll 2
            for (int k = 0; k < KQ; k += 4) {
                LOAD_C(c1A, c1B, k + 1);
                #pragma unroll
                for (int r = 0; r < 8; r++) rvx[r] = rfA[r].x;
                GEMM_STEP(rvx, c0A, c0B);

                LOAD_C(c0A, c0B, k + 2);
                LOAD_RF(rfB, k + 2);
                #pragma unroll
                for (int r = 0; r < 8; r++) rvx[r] = rfA[r].y;
                GEMM_STEP(rvx, c1A, c1B);

                LOAD_C(c1A, c1B, k + 3);
                #pragma unroll
                for (int r = 0; r < 8; r++) rvx[r] = rfB[r].x;
                GEMM_STEP(rvx, c0A, c0B);

                int kn = (k + 4 < KQ) ? (k + 4) : 0;   // tail: harmless reload
                LOAD_C(c0A, c0B, kn);
                LOAD_RF(rfA, kn);
                #pragma unroll
                for (int r = 0; r < 8; r++) rvx[r] = rfB[r].y;
                GEMM_STEP(rvx, c1A, c1B);
            }
            __syncthreads();   // all warps done reading this buffer

            if (c + 2 < NCHUNK) {
                const float* g = g_cbT + (size_t)(c + 2) * CHUNKF;
                float*       s = shBuf + (c & 1) * CHUNKF;
                #pragma unroll
                for (int i = 0; i < CHUNKF / 4 / TPB; i++)
                    cp16(s + (size_t)(tid + i * TPB) * 4, g + (size_t)(tid + i * TPB) * 4);
            }
            asm volatile("cp.async.commit_group;");
        }

        // ---- per-row argmin of dist = -2*dot + cnorm (jax tie-break: first min) ----
        const float* cnl = shCn + l * KCB;
        float4 cn0 = *(const float4*)(cnl + e0);
        float4 cn1 = *(const float4*)(cnl + 128 + e0);
        float cns[8] = {cn0.x, cn0.y, cn0.z, cn0.w, cn1.x, cn1.y, cn1.z, cn1.w};

        #pragma unroll
        for (int r = 0; r < 8; r++) {
            float bestd = 3.402823466e38f;
            int   besti = 0x7fffffff;
            #pragma unroll
            for (int j = 0; j < 8; j++) {
                unsigned long long a = acc[r][j >> 1];
                unsigned u = (j & 1) ? (unsigned)(a >> 32) : (unsigned)a;
                float d = fmaf(-2.0f, __uint_as_float(u), cns[j]);
                int idx = (j < 4) ? (e0 + j) : (128 + e0 + (j - 4));
                if (d < bestd) { bestd = d; besti = idx; }
            }
            #pragma unroll
            for (int off = 16; off > 0; off >>= 1) {
                float od = __shfl_xor_sync(0xffffffffu, bestd, off);
                int   oi = __shfl_xor_sync(0xffffffffu, besti, off);
                if (od < bestd || (od == bestd && oi < besti)) { bestd = od; besti = oi; }
            }
            // gather selected codeword from global (L2-hot), update residual
            // (rows are warp-private -> no barrier needed)
            const float4 cv =
                *(((const float4*)(cb + ((size_t)(l * KCB + besti) << 7))) + lane);
            float4* rp = ((float4*)(shRes + (rbase + r) * DIM)) + lane;
            float4 rv = *rp;
            rv.x -= cv.x; rv.y -= cv.y; rv.z -= cv.z; rv.w -= cv.w;
            *rp = rv;
            if (write_codes && lane == 0)
                out_codes[(row0 + rbase + r) * NLEV + l] = (float)besti;
        }
    }

    // ---- recon = x - residual_final ----
    __syncthreads();
    float4* o4 = (float4*)(out_recon + row0 * DIM);
    #pragma unroll
    for (int i = 0; i < (ROWS * DIM / 4) / TPB; i++) {
        float4 xv = x4[tid + i * TPB];
        float4 rv = res4[tid + i * TPB];
        o4[tid + i * TPB] = make_float4(xv.x - rv.x, xv.y - rv.y, xv.z - rv.z, xv.w - rv.w);
    }
}

// ---------------------------------------------------------------------------
extern "C" void kernel_launch(void* const* d_in, const int* in_sizes, int n_in,
                              void* d_out, int out_size) {
    const float* x  = (const float*)d_in[0];
    const float* cb = (const float*)d_in[1];
    int nx = in_sizes[0];
    int nc = (n_in > 1) ? in_sizes[1] : 0;
    if (nx == NLEV * KCB * DIM && nc != NLEV * KCB * DIM) {
        const float* t = x; x = cb; cb = t;
        int ts = nx; nx = nc; nc = ts;
    }
    const int B = nx / DIM;

    float* out       = (float*)d_out;
    float* out_codes = out + (size_t)B * DIM;
    int write_codes  = (out_size >= B * DIM + B * NLEV) ? 1 : 0;

    const int prep_total = NLEV * KCB * DIM;
    rq_prep_kernel<<<(prep_total + 255) / 256, 256>>>(cb);

    size_t smem = (size_t)(2 * CHUNKF + ROWS * DIM + NLEV * KCB) * sizeof(float); // 53,248 B
    cudaFuncSetAttribute(rq_main_kernel,
                         cudaFuncAttributeMaxDynamicSharedMemorySize, (int)smem);
    rq_main_kernel<<<B / ROWS, TPB, smem>>>(x, cb, out, out_codes, write_codes);
}